// round 12
// baseline (speedup 1.0000x reference)
#include <cuda_runtime.h>
#include <cstdint>
#include <math.h>

// ---------------------------------------------------------------------------
// Shapes (fixed): tokens T=8192, H=4096, I=14336
// ---------------------------------------------------------------------------
#define HDIM 4096
#define IDIM 14336
#define TH   0.5f
#define BAND 0.008f                 // borderline-mask band on |u*a| around TH

#define KT   64                     // k per smem chunk (64 int8 = 64 B/limb-row)
#define RB   80                     // smem row stride bytes (64 data + 16 pad)

// int8 2-limb planes + per-row scales + fp32 act scratch
__device__ float       g_act[117440512ull];     // 8192 x 14336 fp32
__device__ signed char g_xh [33554432ull],  g_xl [33554432ull];    // x
__device__ signed char g_wuh[58720256ull],  g_wul[58720256ull];    // w_up
__device__ signed char g_wgh[58720256ull],  g_wgl[58720256ull];    // w_gate
__device__ signed char g_wdh[58720256ull],  g_wdl[58720256ull];    // w_down
__device__ signed char g_ah [117440512ull], g_al [117440512ull];   // act
__device__ float g_sx[8192], g_swu[14336], g_swg[14336], g_swd[4096], g_sa[8192];

// ---------------------------------------------------------------------------
// helpers
// ---------------------------------------------------------------------------
__device__ __forceinline__ uint32_t smem_u32(const void* p) {
    uint32_t a;
    asm("{ .reg .u64 t; cvta.to.shared.u64 t, %1; cvt.u32.u64 %0, t; }" : "=r"(a) : "l"(p));
    return a;
}
__device__ __forceinline__ void cp_async16(uint32_t dst, const void* src) {
    asm volatile("cp.async.cg.shared.global [%0], [%1], 16;" :: "r"(dst), "l"(src) : "memory");
}
__device__ __forceinline__ void cp_commit() {
    asm volatile("cp.async.commit_group;" ::: "memory");
}
template <int N> __device__ __forceinline__ void cp_wait() {
    asm volatile("cp.async.wait_group %0;" :: "n"(N) : "memory");
}

// m16n8k32 s8 IMMA, s32 accumulate
__device__ __forceinline__ void imma32(int* c, const uint32_t* a, const uint32_t* b) {
    asm volatile(
        "mma.sync.aligned.m16n8k32.row.col.s32.s8.s8.s32 "
        "{%0,%1,%2,%3}, {%4,%5,%6,%7}, {%8,%9}, {%0,%1,%2,%3};"
        : "+r"(c[0]), "+r"(c[1]), "+r"(c[2]), "+r"(c[3])
        : "r"(a[0]), "r"(a[1]), "r"(a[2]), "r"(a[3]), "r"(b[0]), "r"(b[1]));
}

__device__ __forceinline__ float masked_silu(float u, float g, float a) {
    float o = 0.f;
    if (fabsf(u * a) >= TH) o = u * (g / (1.f + expf(-g)));
    return o;
}

// reconstruct: q_a*q_b*(65536*hh + 256*mid)
__device__ __forceinline__ float comb(int hh, int mid) {
    return 256.f * fmaf(256.f, (float)hh, (float)mid);
}

// exact fp32 dot(x_row, wu_row) over HDIM, warp-cooperative
__device__ __noinline__ float warp_dot(const float* __restrict__ xr,
                                       const float* __restrict__ wr, int lane) {
    const float4* x4 = (const float4*)xr;
    const float4* w4 = (const float4*)wr;
    float s = 0.f;
#pragma unroll 4
    for (int i = lane; i < HDIM / 4; i += 32) {
        float4 a = x4[i], b = w4[i];
        s = fmaf(a.x, b.x, s); s = fmaf(a.y, b.y, s);
        s = fmaf(a.z, b.z, s); s = fmaf(a.w, b.w, s);
    }
#pragma unroll
    for (int off = 16; off; off >>= 1) s += __shfl_xor_sync(0xffffffffu, s, off);
    return s;
}

// ---------------------------------------------------------------------------
// qrow: per-row 16-bit quantization into two s8 limbs + float scale.
// v = q*(256*hi + lo), q = rowmax/32639, hi/lo in [-128,127].
// ---------------------------------------------------------------------------
__global__ __launch_bounds__(256)
void qrow(const float* __restrict__ src, int K,
          signed char* __restrict__ hip, signed char* __restrict__ lop,
          float* __restrict__ sc)
{
    __shared__ float red[8];
    __shared__ float sinv;
    const int row = blockIdx.x;
    const int tid = threadIdx.x;
    const float4* s4 = (const float4*)(src + (size_t)row * K);
    const int n4 = K >> 2;
    float m = 0.f;
    for (int i = tid; i < n4; i += 256) {
        float4 v = s4[i];
        m = fmaxf(m, fmaxf(fmaxf(fabsf(v.x), fabsf(v.y)), fmaxf(fabsf(v.z), fabsf(v.w))));
    }
#pragma unroll
    for (int o = 16; o; o >>= 1) m = fmaxf(m, __shfl_xor_sync(0xffffffffu, m, o));
    if ((tid & 31) == 0) red[tid >> 5] = m;
    __syncthreads();
    if (tid == 0) {
        float mm = red[0];
#pragma unroll
        for (int i = 1; i < 8; ++i) mm = fmaxf(mm, red[i]);
        float q = fmaxf(mm, 1e-20f) / 32639.f;
        sc[row] = q;
        sinv = 1.f / q;
    }
    __syncthreads();
    const float inv = sinv;
    char4* h4 = (char4*)(hip + (size_t)row * K);
    char4* l4 = (char4*)(lop + (size_t)row * K);
    for (int i = tid; i < n4; i += 256) {
        float4 v = s4[i];
        int q0 = __float2int_rn(v.x * inv);
        int q1 = __float2int_rn(v.y * inv);
        int q2 = __float2int_rn(v.z * inv);
        int q3 = __float2int_rn(v.w * inv);
        q0 = max(-32639, min(32639, q0)); q1 = max(-32639, min(32639, q1));
        q2 = max(-32639, min(32639, q2)); q3 = max(-32639, min(32639, q3));
        int h0 = (q0 + 128) >> 8, h1 = (q1 + 128) >> 8;
        int h2 = (q2 + 128) >> 8, h3 = (q3 + 128) >> 8;
        h4[i] = make_char4((signed char)h0, (signed char)h1, (signed char)h2, (signed char)h3);
        l4[i] = make_char4((signed char)(q0 - (h0 << 8)), (signed char)(q1 - (h1 << 8)),
                           (signed char)(q2 - (h2 << 8)), (signed char)(q3 - (h3 << 8)));
    }
}

// ---------------------------------------------------------------------------
// P1: up/gate int8 2-limb fused GEMM -> mask (band-recomputed) -> act fp32
// CTA 64x64, 4 warps (2x2) @ warp 32x32, KT=64, 3-stage, 2 CTAs/SM.
// ---------------------------------------------------------------------------
#define P1_STAGE 30720   // xh 0, xl 5120, uh 10240, ul 15360, gh 20480, gl 25600
#define P1_SMEM (3 * P1_STAGE)   // 92160

__global__ __launch_bounds__(128, 2)
void p1_kernel(const signed char* __restrict__ xh, const signed char* __restrict__ xl,
               const signed char* __restrict__ wuh, const signed char* __restrict__ wul,
               const signed char* __restrict__ wgh, const signed char* __restrict__ wgl,
               const float* __restrict__ sx, const float* __restrict__ swu,
               const float* __restrict__ swg, const float* __restrict__ ag,
               const float* __restrict__ x_orig, const float* __restrict__ wu_orig,
               float* __restrict__ act)
{
    extern __shared__ char smc[];
    const uint32_t sb = smem_u32(smc);

    const int per = 16 * 224;                 // 16 m-tiles x 224 n-tiles
    const int grp = blockIdx.x / per;
    const int w   = blockIdx.x % per;
    const int m0  = (grp * 16 + (w % 16)) * 64;
    const int n0  = (w / 16) * 64;

    const int tid  = threadIdx.x;
    const int wid  = tid >> 5;
    const int lane = tid & 31;
    const int wm   = wid >> 1;      // 0..1 (M, 32 rows)
    const int wn   = wid & 1;       // 0..1 (N, 32 cols)
    const int ar   = lane >> 2;
    const int ac   = lane & 3;

    int uhh[2][4][4], umm[2][4][4], ghh[2][4][4], gmm[2][4][4];
#pragma unroll
    for (int t = 0; t < 2; ++t)
#pragma unroll
        for (int u = 0; u < 4; ++u)
#pragma unroll
            for (int q = 0; q < 4; ++q) {
                uhh[t][u][q] = 0; umm[t][u][q] = 0;
                ghh[t][u][q] = 0; gmm[t][u][q] = 0;
            }

    const int NCH = HDIM / KT;      // 64
    const int rB = tid & 63;
    const int limbB = ((tid >> 6) & 1);   // used with q parity below

    auto load_chunk = [&](int ch) {
        const uint32_t so = sb + (uint32_t)((ch % 3) * P1_STAGE);
        const size_t ko = (size_t)ch * KT;
        // x: 64 rows x 2 limbs x 4 granules = 512; 4 iters
#pragma unroll
        for (int q = 0; q < 4; ++q) {
            int limb = q >> 1;
            int c = ((q & 1) << 1) | (tid >> 6);
            const signed char* p = limb ? xl : xh;
            cp_async16(so + (uint32_t)(limb * 5120 + rB * RB + c * 16),
                       p + (size_t)(m0 + rB) * HDIM + ko + c * 16);
        }
#pragma unroll
        for (int q = 0; q < 4; ++q) {
            int limb = q >> 1;
            int c = ((q & 1) << 1) | (tid >> 6);
            const signed char* p = limb ? wul : wuh;
            cp_async16(so + (uint32_t)(10240 + limb * 5120 + rB * RB + c * 16),
                       p + (size_t)(n0 + rB) * HDIM + ko + c * 16);
        }
#pragma unroll
        for (int q = 0; q < 4; ++q) {
            int limb = q >> 1;
            int c = ((q & 1) << 1) | (tid >> 6);
            const signed char* p = limb ? wgl : wgh;
            cp_async16(so + (uint32_t)(20480 + limb * 5120 + rB * RB + c * 16),
                       p + (size_t)(n0 + rB) * HDIM + ko + c * 16);
        }
        cp_commit();
    };

    load_chunk(0);
    load_chunk(1);

    for (int ch = 0; ch < NCH; ++ch) {
        cp_wait<1>();
        __syncthreads();
        if (ch + 2 < NCH) load_chunk(ch + 2);
        else cp_commit();

        const char* st = smc + (ch % 3) * P1_STAGE;

#pragma unroll
        for (int s = 0; s < 2; ++s) {
            const int koff = 32 * s + 4 * ac;
            uint32_t AH[2][4], AL[2][4];
#pragma unroll
            for (int t = 0; t < 2; ++t) {
                const int rb0 = (wm * 32 + t * 16 + ar) * RB;
                AH[t][0] = *(const uint32_t*)(st + rb0 + koff);
                AH[t][1] = *(const uint32_t*)(st + rb0 + 8 * RB + koff);
                AH[t][2] = *(const uint32_t*)(st + rb0 + koff + 16);
                AH[t][3] = *(const uint32_t*)(st + rb0 + 8 * RB + koff + 16);
                AL[t][0] = *(const uint32_t*)(st + 5120 + rb0 + koff);
                AL[t][1] = *(const uint32_t*)(st + 5120 + rb0 + 8 * RB + koff);
                AL[t][2] = *(const uint32_t*)(st + 5120 + rb0 + koff + 16);
                AL[t][3] = *(const uint32_t*)(st + 5120 + rb0 + 8 * RB + koff + 16);
            }
            uint32_t UH[4][2], UL[4][2], GH[4][2], GL[4][2];
#pragma unroll
            for (int u = 0; u < 4; ++u) {
                const int nb0 = (wn * 32 + u * 8 + ar) * RB;
                UH[u][0] = *(const uint32_t*)(st + 10240 + nb0 + koff);
                UH[u][1] = *(const uint32_t*)(st + 10240 + nb0 + koff + 16);
                UL[u][0] = *(const uint32_t*)(st + 15360 + nb0 + koff);
                UL[u][1] = *(const uint32_t*)(st + 15360 + nb0 + koff + 16);
                GH[u][0] = *(const uint32_t*)(st + 20480 + nb0 + koff);
                GH[u][1] = *(const uint32_t*)(st + 20480 + nb0 + koff + 16);
                GL[u][0] = *(const uint32_t*)(st + 25600 + nb0 + koff);
                GL[u][1] = *(const uint32_t*)(st + 25600 + nb0 + koff + 16);
            }
#pragma unroll
            for (int t = 0; t < 2; ++t)
#pragma unroll
                for (int u = 0; u < 4; ++u) {
                    imma32(uhh[t][u], AH[t], UH[u]);
                    imma32(umm[t][u], AH[t], UL[u]);
                    imma32(umm[t][u], AL[t], UH[u]);
                    imma32(ghh[t][u], AH[t], GH[u]);
                    imma32(gmm[t][u], AH[t], GL[u]);
                    imma32(gmm[t][u], AL[t], GH[u]);
                }
        }
    }

    // ---------------- epilogue: scales, band recompute, mask+silu ----------
#pragma unroll
    for (int t = 0; t < 2; ++t) {
#pragma unroll
        for (int u = 0; u < 4; ++u) {
            const int gr = m0 + wm * 32 + t * 16 + ar;
            const int gc = n0 + wn * 32 + u * 8 + 2 * ac;
            const float sxr0 = __ldg(sx + gr), sxr1 = __ldg(sx + gr + 8);
            const float su0 = __ldg(swu + gc), su1 = __ldg(swu + gc + 1);
            const float sg0 = __ldg(swg + gc), sg1 = __ldg(swg + gc + 1);
            float uv[4], gv[4];
            uv[0] = sxr0 * su0 * comb(uhh[t][u][0], umm[t][u][0]);
            uv[1] = sxr0 * su1 * comb(uhh[t][u][1], umm[t][u][1]);
            uv[2] = sxr1 * su0 * comb(uhh[t][u][2], umm[t][u][2]);
            uv[3] = sxr1 * su1 * comb(uhh[t][u][3], umm[t][u][3]);
            gv[0] = sxr0 * sg0 * comb(ghh[t][u][0], gmm[t][u][0]);
            gv[1] = sxr0 * sg1 * comb(ghh[t][u][1], gmm[t][u][1]);
            gv[2] = sxr1 * sg0 * comb(ghh[t][u][2], gmm[t][u][2]);
            gv[3] = sxr1 * sg1 * comb(ghh[t][u][3], gmm[t][u][3]);
            const float a0 = __ldg(ag + gc), a1 = __ldg(ag + gc + 1);
            float av[4] = {a0, a1, a0, a1};
            int   rw[4] = {gr, gr, gr + 8, gr + 8};
            int   cl[4] = {gc, gc + 1, gc, gc + 1};
#pragma unroll
            for (int q = 0; q < 4; ++q) {
                bool flag = fabsf(fabsf(uv[q] * av[q]) - TH) < BAND;
                unsigned bal = __ballot_sync(0xffffffffu, flag);
                while (bal) {
                    int src = __ffs(bal) - 1; bal &= bal - 1;
                    int rr = __shfl_sync(0xffffffffu, rw[q], src);
                    int cc = __shfl_sync(0xffffffffu, cl[q], src);
                    float s = warp_dot(x_orig + (size_t)rr * HDIM,
                                       wu_orig + (size_t)cc * HDIM, lane);
                    if (lane == src) uv[q] = s;
                }
            }
            float2 v0, v1;
            v0.x = masked_silu(uv[0], gv[0], av[0]);
            v0.y = masked_silu(uv[1], gv[1], av[1]);
            v1.x = masked_silu(uv[2], gv[2], av[2]);
            v1.y = masked_silu(uv[3], gv[3], av[3]);
            *(float2*)&act[(size_t)gr * IDIM + gc]       = v0;
            *(float2*)&act[(size_t)(gr + 8) * IDIM + gc] = v1;
        }
    }
}

// ---------------------------------------------------------------------------
// P2: out = act @ wd^T, int8 2-limb. CTA 128x64, 4 warps (2x2) @ warp 64x32.
// KT=64, 3-stage, 2 CTAs/SM.
// ---------------------------------------------------------------------------
#define P2_STAGE 30720   // ah 0 (128x80), al 10240, bh 20480 (64x80), bl 25600
#define P2_SMEM (3 * P2_STAGE)   // 92160

__global__ __launch_bounds__(128, 2)
void p2_kernel(const signed char* __restrict__ ah, const signed char* __restrict__ al,
               const signed char* __restrict__ wdh, const signed char* __restrict__ wdl,
               const float* __restrict__ sa, const float* __restrict__ swd,
               float* __restrict__ out)
{
    extern __shared__ char smc[];
    const uint32_t sb = smem_u32(smc);

    const int per = 16 * 64;                  // 16 m-tiles x 64 n-tiles
    const int grp = blockIdx.x / per;
    const int w   = blockIdx.x % per;
    const int m0  = (grp * 16 + (w % 16)) * 128;
    const int n0  = (w / 16) * 64;

    const int tid  = threadIdx.x;
    const int wid  = tid >> 5;
    const int lane = tid & 31;
    const int wm   = wid >> 1;      // 0..1 (M, 64 rows)
    const int wn   = wid & 1;       // 0..1 (N, 32 cols)
    const int ar   = lane >> 2;
    const int ac   = lane & 3;

    int hh[4][4][4], mm[4][4][4];
#pragma unroll
    for (int t = 0; t < 4; ++t)
#pragma unroll
        for (int u = 0; u < 4; ++u)
#pragma unroll
            for (int q = 0; q < 4; ++q) { hh[t][u][q] = 0; mm[t][u][q] = 0; }

    const int NCH = IDIM / KT;      // 224
    const int rB = tid & 63;

    auto load_chunk = [&](int ch) {
        const uint32_t so = sb + (uint32_t)((ch % 3) * P2_STAGE);
        const size_t ko = (size_t)ch * KT;
        // A (act): 128 rows x 2 limbs x 4 granules = 1024; 8 iters, r = tid
#pragma unroll
        for (int q = 0; q < 8; ++q) {
            int limb = q >> 2;
            int c = q & 3;
            const signed char* p = limb ? al : ah;
            cp_async16(so + (uint32_t)(limb * 10240 + tid * RB + c * 16),
                       p + (size_t)(m0 + tid) * IDIM + ko + c * 16);
        }
        // B (wd): 64 rows x 2 limbs x 4 granules = 512; 4 iters
#pragma unroll
        for (int q = 0; q < 4; ++q) {
            int limb = q >> 1;
            int c = ((q & 1) << 1) | (tid >> 6);
            const signed char* p = limb ? wdl : wdh;
            cp_async16(so + (uint32_t)(20480 + limb * 5120 + rB * RB + c * 16),
                       p + (size_t)(n0 + rB) * IDIM + ko + c * 16);
        }
        cp_commit();
    };

    load_chunk(0);
    load_chunk(1);

    for (int ch = 0; ch < NCH; ++ch) {
        cp_wait<1>();
        __syncthreads();
        if (ch + 2 < NCH) load_chunk(ch + 2);
        else cp_commit();

        const char* st = smc + (ch % 3) * P2_STAGE;

#pragma unroll
        for (int s = 0; s < 2; ++s) {
            const int koff = 32 * s + 4 * ac;
            uint32_t AH[4][4], AL[4][4];
#pragma unroll
            for (int t = 0; t < 4; ++t) {
                const int rb0 = (wm * 64 + t * 16 + ar) * RB;
                AH[t][0] = *(const uint32_t*)(st + rb0 + koff);
                AH[t][1] = *(const uint32_t*)(st + rb0 + 8 * RB + koff);
                AH[t][2] = *(const uint32_t*)(st + rb0 + koff + 16);
                AH[t][3] = *(const uint32_t*)(st + rb0 + 8 * RB + koff + 16);
                AL[t][0] = *(const uint32_t*)(st + 10240 + rb0 + koff);
                AL[t][1] = *(const uint32_t*)(st + 10240 + rb0 + 8 * RB + koff);
                AL[t][2] = *(const uint32_t*)(st + 10240 + rb0 + koff + 16);
                AL[t][3] = *(const uint32_t*)(st + 10240 + rb0 + 8 * RB + koff + 16);
            }
            uint32_t BH[4][2], BL[4][2];
#pragma unroll
            for (int u = 0; u < 4; ++u) {
                const int nb0 = (wn * 32 + u * 8 + ar) * RB;
                BH[u][0] = *(const uint32_t*)(st + 20480 + nb0 + koff);
                BH[u][1] = *(const uint32_t*)(st + 20480 + nb0 + koff + 16);
                BL[u][0] = *(const uint32_t*)(st + 25600 + nb0 + koff);
                BL[u][1] = *(const uint32_t*)(st + 25600 + nb0 + koff + 16);
            }
#pragma unroll
            for (int t = 0; t < 4; ++t)
#pragma unroll
                for (int u = 0; u < 4; ++u) {
                    imma32(hh[t][u], AH[t], BH[u]);
                    imma32(mm[t][u], AH[t], BL[u]);
                    imma32(mm[t][u], AL[t], BH[u]);
                }
        }
    }

#pragma unroll
    for (int t = 0; t < 4; ++t) {
#pragma unroll
        for (int u = 0; u < 4; ++u) {
            const int gr = m0 + wm * 64 + t * 16 + ar;
            const int gc = n0 + wn * 32 + u * 8 + 2 * ac;
            const float sa0 = __ldg(sa + gr), sa1 = __ldg(sa + gr + 8);
            const float sd0 = __ldg(swd + gc), sd1 = __ldg(swd + gc + 1);
            float2 v0, v1;
            v0.x = sa0 * sd0 * comb(hh[t][u][0], mm[t][u][0]);
            v0.y = sa0 * sd1 * comb(hh[t][u][1], mm[t][u][1]);
            v1.x = sa1 * sd0 * comb(hh[t][u][2], mm[t][u][2]);
            v1.y = sa1 * sd1 * comb(hh[t][u][3], mm[t][u][3]);
            *(float2*)&out[(size_t)gr * HDIM + gc]       = v0;
            *(float2*)&out[(size_t)(gr + 8) * HDIM + gc] = v1;
        }
    }
}

// ---------------------------------------------------------------------------
// launch: inputs x, w_gate, w_up, w_down, avg_gate
// ---------------------------------------------------------------------------
extern "C" void kernel_launch(void* const* d_in, const int* in_sizes, int n_in,
                              void* d_out, int out_size)
{
    const float* x  = (const float*)d_in[0];
    const float* wg = (const float*)d_in[1];
    const float* wu = (const float*)d_in[2];
    const float* wd = (const float*)d_in[3];
    const float* ag = (const float*)d_in[4];
    float* out = (float*)d_out;

    float *act, *sx, *swu, *swg, *swd, *sa;
    signed char *xh, *xl, *wuh, *wul, *wgh, *wgl, *wdh, *wdl, *ah, *al;
    cudaGetSymbolAddress((void**)&act, g_act);
    cudaGetSymbolAddress((void**)&xh,  g_xh);  cudaGetSymbolAddress((void**)&xl,  g_xl);
    cudaGetSymbolAddress((void**)&wuh, g_wuh); cudaGetSymbolAddress((void**)&wul, g_wul);
    cudaGetSymbolAddress((void**)&wgh, g_wgh); cudaGetSymbolAddress((void**)&wgl, g_wgl);
    cudaGetSymbolAddress((void**)&wdh, g_wdh); cudaGetSymbolAddress((void**)&wdl, g_wdl);
    cudaGetSymbolAddress((void**)&ah,  g_ah);  cudaGetSymbolAddress((void**)&al,  g_al);
    cudaGetSymbolAddress((void**)&sx,  g_sx);  cudaGetSymbolAddress((void**)&swu, g_swu);
    cudaGetSymbolAddress((void**)&swg, g_swg); cudaGetSymbolAddress((void**)&swd, g_swd);
    cudaGetSymbolAddress((void**)&sa,  g_sa);

    // quantize all operands (per-row, 2 limbs)
    qrow<<<8192,  256>>>(x,  HDIM, xh,  xl,  sx);
    qrow<<<14336, 256>>>(wu, HDIM, wuh, wul, swu);
    qrow<<<14336, 256>>>(wg, HDIM, wgh, wgl, swg);
    qrow<<<4096,  256>>>(wd, IDIM, wdh, wdl, swd);

    cudaFuncSetAttribute(p1_kernel, cudaFuncAttributeMaxDynamicSharedMemorySize, P1_SMEM);
    cudaFuncSetAttribute(p2_kernel, cudaFuncAttributeMaxDynamicSharedMemorySize, P2_SMEM);

    // P1: 128 m-tiles(64) x 224 n-tiles(64) = 28672 CTAs
    p1_kernel<<<28672, 128, P1_SMEM>>>(xh, xl, wuh, wul, wgh, wgl,
                                       sx, swu, swg, ag, x, wu, act);
    // quantize act rows
    qrow<<<8192, 256>>>(act, IDIM, ah, al, sa);
    // P2: 64 m-tiles(128) x 64 n-tiles(64) = 4096 CTAs
    p2_kernel<<<4096, 128, P2_SMEM>>>(ah, al, wdh, wdl, sa, swd, out);
}

// round 13
// speedup vs baseline: 4.2253x; 4.2253x over previous
#include <cuda_runtime.h>
#include <cstdint>
#include <math.h>

// ---------------------------------------------------------------------------
// Shapes (fixed): tokens T=8192, H=4096, I=14336
// ---------------------------------------------------------------------------
#define HDIM 4096
#define IDIM 14336
#define TH   0.5f
#define BAND 0.008f                 // borderline-mask band on |u*a| around TH

#define KT   32                     // k per smem chunk (32 floats = 128 B/row)

// scratch (tf32-rounded, column-pair-permuted operands) + act
__device__ float g_act[117440512ull];   // 8192 x 14336 (rounded+permuted)
__device__ float g_xr [33554432ull];    // 8192 x 4096
__device__ float g_wgr[58720256ull];    // 14336 x 4096
__device__ float g_wur[58720256ull];    // 14336 x 4096
__device__ float g_wdr[58720256ull];    // 4096 x 14336

// ---------------------------------------------------------------------------
// helpers
// ---------------------------------------------------------------------------
__device__ __forceinline__ uint32_t smem_u32(const void* p) {
    uint32_t a;
    asm("{ .reg .u64 t; cvta.to.shared.u64 t, %1; cvt.u32.u64 %0, t; }" : "=r"(a) : "l"(p));
    return a;
}
__device__ __forceinline__ float f2tf_f(float x) {   // RNA round to tf32
    uint32_t o;
    asm("cvt.rna.tf32.f32 %0, %1;" : "=r"(o) : "f"(x));
    return __uint_as_float(o);
}
__device__ __forceinline__ void cp_async16(uint32_t dst, const void* src) {
    asm volatile("cp.async.cg.shared.global [%0], [%1], 16;" :: "r"(dst), "l"(src) : "memory");
}
__device__ __forceinline__ void cp_commit() {
    asm volatile("cp.async.commit_group;" ::: "memory");
}
template <int N> __device__ __forceinline__ void cp_wait() {
    asm volatile("cp.async.wait_group %0;" :: "n"(N) : "memory");
}

// m16n8k8 tf32 mma
__device__ __forceinline__ void mma8(float* c, const uint32_t* a, const uint32_t* b) {
    asm volatile(
        "mma.sync.aligned.m16n8k8.row.col.f32.tf32.tf32.f32 "
        "{%0,%1,%2,%3}, {%4,%5,%6,%7}, {%8,%9}, {%0,%1,%2,%3};"
        : "+f"(c[0]), "+f"(c[1]), "+f"(c[2]), "+f"(c[3])
        : "r"(a[0]), "r"(a[1]), "r"(a[2]), "r"(a[3]), "r"(b[0]), "r"(b[1]));
}

__device__ __forceinline__ float masked_silu(float u, float g, float a) {
    float o = 0.f;
    if (fabsf(u * a) >= TH) o = u * (g / (1.f + expf(-g)));
    return o;
}

// exact fp32 dot(x_row, wu_row) over HDIM, warp-cooperative
__device__ __noinline__ float warp_dot(const float* __restrict__ xr,
                                       const float* __restrict__ wr, int lane) {
    const float4* x4 = (const float4*)xr;
    const float4* w4 = (const float4*)wr;
    float s = 0.f;
#pragma unroll 4
    for (int i = lane; i < HDIM / 4; i += 32) {
        float4 a = x4[i], b = w4[i];
        s = fmaf(a.x, b.x, s); s = fmaf(a.y, b.y, s);
        s = fmaf(a.z, b.z, s); s = fmaf(a.w, b.w, s);
    }
#pragma unroll
    for (int off = 16; off; off >>= 1) s += __shfl_xor_sync(0xffffffffu, s, off);
    return s;
}

// ---------------------------------------------------------------------------
// prep: round to tf32 (RNA) + permute each 8-col group to [0,4,1,5,2,6,3,7].
// Single merged launch covering x + wg + wu + wd.
// ---------------------------------------------------------------------------
__device__ __forceinline__ void prep_one(const float* __restrict__ src,
                                         float* __restrict__ dst, size_t i) {
    const float4* s = (const float4*)src + 2 * i;
    float4 lo = s[0], hi = s[1];
    float4 o0, o1;
    o0.x = f2tf_f(lo.x); o0.y = f2tf_f(hi.x); o0.z = f2tf_f(lo.y); o0.w = f2tf_f(hi.y);
    o1.x = f2tf_f(lo.z); o1.y = f2tf_f(hi.z); o1.z = f2tf_f(lo.w); o1.w = f2tf_f(hi.w);
    float4* d = (float4*)dst + 2 * i;
    d[0] = o0; d[1] = o1;
}

#define N8X (8192 * HDIM / 8)       // 4194304
#define N8W (IDIM * HDIM / 8)       // 7340032

__global__ __launch_bounds__(256)
void prep_all(const float* __restrict__ x,  float* __restrict__ xr,
              const float* __restrict__ wg, float* __restrict__ wgr,
              const float* __restrict__ wu, float* __restrict__ wur,
              const float* __restrict__ wd, float* __restrict__ wdr)
{
    int i = blockIdx.x * blockDim.x + threadIdx.x;
    if (i < N8X)                       prep_one(x,  xr,  (size_t)i);
    else if (i < N8X + N8W)            prep_one(wg, wgr, (size_t)(i - N8X));
    else if (i < N8X + 2 * N8W)        prep_one(wu, wur, (size_t)(i - N8X - N8W));
    else if (i < N8X + 3 * N8W)        prep_one(wd, wdr, (size_t)(i - N8X - 2 * N8W));
}

// ---------------------------------------------------------------------------
// Pad-free smem swizzle: tile row r holds 32 floats (128 B). 16B granule c
// (0..7) stored at physical granule c ^ (2*(r&3)).
// ---------------------------------------------------------------------------
#define ROWF 32                     // floats per smem row

// ---------------------------------------------------------------------------
// P1: up = x@wu^T (tf32), gate = x@wg^T (tf32) -> masked act (rounded+permuted)
// CTA 128x64 fused, 4 warps (2x2) @ 64x32. KT=32, 3-stage, 2 CTAs/SM.
// ---------------------------------------------------------------------------
#define P1_STAGE_FLOATS ((128 + 64 + 64) * ROWF)     // 8192 floats = 32768 B
#define P1_SMEM (3 * P1_STAGE_FLOATS * 4)            // 98304 B

__global__ __launch_bounds__(128, 2)
void p1_kernel(const float* __restrict__ xr, const float* __restrict__ wgr,
               const float* __restrict__ wur, const float* __restrict__ ag,
               const float* __restrict__ x_orig, const float* __restrict__ wu_orig,
               float* __restrict__ act)
{
    extern __shared__ float sm[];

    const int per = 16 * 224;                 // 16 m-tiles x 224 n-tiles
    const int grp = blockIdx.x / per;
    const int w   = blockIdx.x % per;
    const int m0  = (grp * 16 + (w % 16)) * 128;
    const int n0  = (w / 16) * 64;

    const int tid  = threadIdx.x;
    const int wid  = tid >> 5;
    const int lane = tid & 31;
    const int wm   = wid >> 1;      // 0..1 (M, 64 rows)
    const int wn   = wid & 1;       // 0..1 (N, 32 cols)
    const int ar   = lane >> 2;
    const int ac   = lane & 3;
    const int sw2  = (ar & 3) << 1; // swizzle term
    const int aci  = ac >> 1;
    const int kin  = (ac & 1) << 1;

    float upc[4][4][4];
    float gtc[4][4][4];
#pragma unroll
    for (int t = 0; t < 4; ++t)
#pragma unroll
        for (int u = 0; u < 4; ++u)
#pragma unroll
            for (int q = 0; q < 4; ++q) { upc[t][u][q] = 0.f; gtc[t][u][q] = 0.f; }

    const int NCH = HDIM / KT;      // 128

    const uint32_t sXa  = smem_u32(sm);
    const uint32_t sWua = sXa + 128 * ROWF * 4;
    const uint32_t sWga = sWua + 64 * ROWF * 4;

    auto sts_off = [](int r, int c) -> uint32_t {
        return (uint32_t)(r * 128 + ((c ^ ((r & 3) << 1)) << 4));
    };

    auto load_chunk = [&](int ch) {
        const uint32_t so = (uint32_t)((ch % 3) * P1_STAGE_FLOATS * 4);
        const float* xs  = xr  + (size_t)m0 * HDIM + ch * KT;
        const float* wus = wur + (size_t)n0 * HDIM + ch * KT;
        const float* wgs = wgr + (size_t)n0 * HDIM + ch * KT;
#pragma unroll
        for (int q = 0; q < 8; ++q) {      // x: 1024 x 16B / 128 threads
            int lin = q * 128 + tid;
            int r = lin >> 3, c = lin & 7;
            cp_async16(sXa + so + sts_off(r, c), xs + (size_t)r * HDIM + c * 4);
        }
#pragma unroll
        for (int q = 0; q < 4; ++q) {      // wu: 512 x 16B
            int lin = q * 128 + tid;
            int r = lin >> 3, c = lin & 7;
            cp_async16(sWua + so + sts_off(r, c), wus + (size_t)r * HDIM + c * 4);
        }
#pragma unroll
        for (int q = 0; q < 4; ++q) {      // wg: 512 x 16B
            int lin = q * 128 + tid;
            int r = lin >> 3, c = lin & 7;
            cp_async16(sWga + so + sts_off(r, c), wgs + (size_t)r * HDIM + c * 4);
        }
        cp_commit();
    };

    load_chunk(0);
    load_chunk(1);

    for (int ch = 0; ch < NCH; ++ch) {
        cp_wait<1>();                       // chunk ch ready; ch+1 may be in flight
        __syncthreads();
        if (ch + 2 < NCH) load_chunk(ch + 2);
        else cp_commit();                   // empty group keeps wait<1> invariant

        const float* base = sm + (ch % 3) * P1_STAGE_FLOATS;
        const float* sX  = base;
        const float* sWu = base + 128 * ROWF;
        const float* sWg = base + 192 * ROWF;

#pragma unroll
        for (int s8 = 0; s8 < 4; ++s8) {
            const int cl = 2 * s8 + aci;
            const int co = ((cl ^ sw2) << 2) + kin;   // swizzled column offset
            uint32_t xf[4][4];
#pragma unroll
            for (int t = 0; t < 4; ++t) {
                const int mb = wm * 64 + t * 16;
                float2 p0 = *(const float2*)&sX[(mb + ar)     * ROWF + co];
                float2 p1 = *(const float2*)&sX[(mb + ar + 8) * ROWF + co];
                xf[t][0] = __float_as_uint(p0.x);
                xf[t][1] = __float_as_uint(p1.x);
                xf[t][2] = __float_as_uint(p0.y);
                xf[t][3] = __float_as_uint(p1.y);
            }
            uint32_t uf[4][2], gf[4][2];
#pragma unroll
            for (int u = 0; u < 4; ++u) {
                const int nb = wn * 32 + u * 8;
                float2 pu = *(const float2*)&sWu[(nb + ar) * ROWF + co];
                float2 pg = *(const float2*)&sWg[(nb + ar) * ROWF + co];
                uf[u][0] = __float_as_uint(pu.x); uf[u][1] = __float_as_uint(pu.y);
                gf[u][0] = __float_as_uint(pg.x); gf[u][1] = __float_as_uint(pg.y);
            }
#pragma unroll
            for (int t = 0; t < 4; ++t)
#pragma unroll
                for (int u = 0; u < 4; ++u) {
                    mma8(upc[t][u], xf[t], uf[u]);
                    mma8(gtc[t][u], xf[t], gf[u]);
                }
        }
    }

    // ---------------- epilogue: borderline recompute + mask + silu ----------
    const int pA = (ac < 2) ? 4 * ac : 4 * ac - 7;      // phys of logical 2*ac
    const int pB = (ac < 2) ? 4 * ac + 2 : 4 * ac - 5;  // phys of logical 2*ac+1
#pragma unroll
    for (int t = 0; t < 4; ++t) {
#pragma unroll
        for (int u = 0; u < 4; ++u) {
            const int gr = m0 + wm * 64 + t * 16 + ar;
            const int gb = n0 + wn * 32 + u * 8;        // 8-aligned group base
            const int gc = gb + 2 * ac;                 // logical column
            const float a0 = __ldg(ag + gc);
            const float a1 = __ldg(ag + gc + 1);
            float uv[4] = {upc[t][u][0], upc[t][u][1], upc[t][u][2], upc[t][u][3]};
            float gv[4] = {gtc[t][u][0], gtc[t][u][1], gtc[t][u][2], gtc[t][u][3]};
            float av[4] = {a0, a1, a0, a1};
            int   rw[4] = {gr, gr, gr + 8, gr + 8};
            int   cl4[4] = {gc, gc + 1, gc, gc + 1};
#pragma unroll
            for (int q = 0; q < 4; ++q) {
                bool flag = fabsf(fabsf(uv[q] * av[q]) - TH) < BAND;
                unsigned bal = __ballot_sync(0xffffffffu, flag);
                while (bal) {
                    int src = __ffs(bal) - 1; bal &= bal - 1;
                    int rr = __shfl_sync(0xffffffffu, rw[q], src);
                    int cc = __shfl_sync(0xffffffffu, cl4[q], src);
                    float s = warp_dot(x_orig + (size_t)rr * HDIM,
                                       wu_orig + (size_t)cc * HDIM, lane);
                    if (lane == src) uv[q] = s;
                }
            }
            float r0 = f2tf_f(masked_silu(uv[0], gv[0], av[0]));
            float r1 = f2tf_f(masked_silu(uv[1], gv[1], av[1]));
            float r2 = f2tf_f(masked_silu(uv[2], gv[2], av[2]));
            float r3 = f2tf_f(masked_silu(uv[3], gv[3], av[3]));
            float* row0 = &act[(size_t)gr * IDIM + gb];
            float* row1 = &act[(size_t)(gr + 8) * IDIM + gb];
            row0[pA] = r0; row0[pB] = r1;
            row1[pA] = r2; row1[pB] = r3;
        }
    }
}

// ---------------------------------------------------------------------------
// P2: out = act @ wd^T (tf32, pre-rounded+permuted)
// CTA 128x128, 4 warps (2x2) @ 64x64. KT=32, 3-stage, 2 CTAs/SM.
// ---------------------------------------------------------------------------
#define P2_STAGE_FLOATS ((128 + 128) * ROWF)         // 8192 floats = 32768 B
#define P2_SMEM (3 * P2_STAGE_FLOATS * 4)            // 98304 B

__global__ __launch_bounds__(128, 2)
void p2_kernel(const float* __restrict__ act, const float* __restrict__ wdr,
               float* __restrict__ out)
{
    extern __shared__ float sm[];

    const int per = 16 * 32;                  // 16 m-tiles x 32 n-tiles
    const int grp = blockIdx.x / per;
    const int w   = blockIdx.x % per;
    const int m0  = (grp * 16 + (w % 16)) * 128;
    const int n0  = (w / 16) * 128;

    const int tid  = threadIdx.x;
    const int wid  = tid >> 5;
    const int lane = tid & 31;
    const int wm   = wid >> 1;      // 0..1 (M, 64 rows)
    const int wn   = wid & 1;       // 0..1 (N, 64 cols)
    const int ar   = lane >> 2;
    const int ac   = lane & 3;
    const int sw2  = (ar & 3) << 1;
    const int aci  = ac >> 1;
    const int kin  = (ac & 1) << 1;

    float acc[4][8][4];
#pragma unroll
    for (int t = 0; t < 4; ++t)
#pragma unroll
        for (int u = 0; u < 8; ++u)
#pragma unroll
            for (int q = 0; q < 4; ++q) acc[t][u][q] = 0.f;

    const int NCH = IDIM / KT;      // 448

    const uint32_t sAa = smem_u32(sm);
    const uint32_t sBa = sAa + 128 * ROWF * 4;

    auto sts_off = [](int r, int c) -> uint32_t {
        return (uint32_t)(r * 128 + ((c ^ ((r & 3) << 1)) << 4));
    };

    auto load_chunk = [&](int ch) {
        const uint32_t so = (uint32_t)((ch % 3) * P2_STAGE_FLOATS * 4);
        const float* as = act + (size_t)m0 * IDIM + ch * KT;
        const float* bs = wdr + (size_t)n0 * IDIM + ch * KT;
#pragma unroll
        for (int q = 0; q < 8; ++q) {      // A: 1024 x 16B / 128 threads
            int lin = q * 128 + tid;
            int r = lin >> 3, c = lin & 7;
            cp_async16(sAa + so + sts_off(r, c), as + (size_t)r * IDIM + c * 4);
        }
#pragma unroll
        for (int q = 0; q < 8; ++q) {      // B: 1024 x 16B
            int lin = q * 128 + tid;
            int r = lin >> 3, c = lin & 7;
            cp_async16(sBa + so + sts_off(r, c), bs + (size_t)r * IDIM + c * 4);
        }
        cp_commit();
    };

    load_chunk(0);
    load_chunk(1);

    for (int ch = 0; ch < NCH; ++ch) {
        cp_wait<1>();
        __syncthreads();
        if (ch + 2 < NCH) load_chunk(ch + 2);
        else cp_commit();

        const float* base = sm + (ch % 3) * P2_STAGE_FLOATS;
        const float* sA = base;
        const float* sB = base + 128 * ROWF;

#pragma unroll
        for (int s8 = 0; s8 < 4; ++s8) {
            const int cl = 2 * s8 + aci;
            const int co = ((cl ^ sw2) << 2) + kin;
            uint32_t af[4][4];
#pragma unroll
            for (int t = 0; t < 4; ++t) {
                const int mb = wm * 64 + t * 16;
                float2 p0 = *(const float2*)&sA[(mb + ar)     * ROWF + co];
                float2 p1 = *(const float2*)&sA[(mb + ar + 8) * ROWF + co];
                af[t][0] = __float_as_uint(p0.x);
                af[t][1] = __float_as_uint(p1.x);
                af[t][2] = __float_as_uint(p0.y);
                af[t][3] = __float_as_uint(p1.y);
            }
            uint32_t bf[8][2];
#pragma unroll
            for (int u = 0; u < 8; ++u) {
                const int nb = wn * 64 + u * 8;
                float2 pb = *(const float2*)&sB[(nb + ar) * ROWF + co];
                bf[u][0] = __float_as_uint(pb.x);
                bf[u][1] = __float_as_uint(pb.y);
            }
#pragma unroll
            for (int t = 0; t < 4; ++t)
#pragma unroll
                for (int u = 0; u < 8; ++u)
                    mma8(acc[t][u], af[t], bf[u]);
        }
    }

#pragma unroll
    for (int t = 0; t < 4; ++t) {
#pragma unroll
        for (int u = 0; u < 8; ++u) {
            const int gr = m0 + wm * 64 + t * 16 + ar;
            const int gc = n0 + wn * 64 + u * 8 + 2 * ac;
            float2 v0, v1;
            v0.x = acc[t][u][0]; v0.y = acc[t][u][1];
            v1.x = acc[t][u][2]; v1.y = acc[t][u][3];
            *(float2*)&out[(size_t)gr * HDIM + gc]       = v0;
            *(float2*)&out[(size_t)(gr + 8) * HDIM + gc] = v1;
        }
    }
}

// ---------------------------------------------------------------------------
// launch: inputs x, w_gate, w_up, w_down, avg_gate
// ---------------------------------------------------------------------------
extern "C" void kernel_launch(void* const* d_in, const int* in_sizes, int n_in,
                              void* d_out, int out_size)
{
    const float* x  = (const float*)d_in[0];
    const float* wg = (const float*)d_in[1];
    const float* wu = (const float*)d_in[2];
    const float* wd = (const float*)d_in[3];
    const float* ag = (const float*)d_in[4];
    float* out = (float*)d_out;

    float *act, *xr, *wgr, *wur, *wdr;
    cudaGetSymbolAddress((void**)&act, g_act);
    cudaGetSymbolAddress((void**)&xr,  g_xr);
    cudaGetSymbolAddress((void**)&wgr, g_wgr);
    cudaGetSymbolAddress((void**)&wur, g_wur);
    cudaGetSymbolAddress((void**)&wdr, g_wdr);

    // prep: round+permute all GEMM operands (single merged launch)
    {
        long long total = (long long)N8X + 3LL * N8W;
        int blocks = (int)((total + 255) / 256);
        prep_all<<<blocks, 256>>>(x, xr, wg, wgr, wu, wur, wd, wdr);
    }

    cudaFuncSetAttribute(p1_kernel, cudaFuncAttributeMaxDynamicSharedMemorySize, P1_SMEM);
    cudaFuncSetAttribute(p2_kernel, cudaFuncAttributeMaxDynamicSharedMemorySize, P2_SMEM);

    // P1: 64 m-tiles x 224 n-tiles = 14336 CTAs
    p1_kernel<<<14336, 128, P1_SMEM>>>(xr, wgr, wur, ag, x, wu, act);
    // P2: 64 m-tiles x 32 n-tiles = 2048 CTAs
    p2_kernel<<<2048, 128, P2_SMEM>>>(act, wdr, out);
}